// round 1
// baseline (speedup 1.0000x reference)
#include <cuda_runtime.h>
#include <math.h>

// Problem dims (fixed by reference)
#define Bdim 4
#define Sdim 2048
#define Edim 1024
#define Hdim 16
#define DKdim 64
#define FFNdim 4096
#define NQdim 8
#define NTOK (Bdim * Sdim)
#define EPSv 1e-5f

// Scratch (alloc-free rule: __device__ globals)
__device__ float g_attn[(size_t)NTOK * Edim];   // 33.5 MB
__device__ float g_h[(size_t)NTOK * Edim];      // 33.5 MB
__device__ float g_qout[NTOK * NQdim];          // 256 KB

// ---------------------------------------------------------------------------
// Attention: per (b,h) pair, flash-style over 64-key tiles with unnormalized
// streaming softmax (no max subtraction needed: scores <= ~15).
// Block: 256 threads = 16x16, each computes a 4x4 micro-tile of a 64x64 tile.
// ---------------------------------------------------------------------------
__global__ void __launch_bounds__(256) attn_kernel(const float* __restrict__ x,
                                                   float* __restrict__ attn) {
    extern __shared__ float sm[];
    float* Qs   = sm;               // [64][65]
    float* Ks   = sm + 64 * 65;     // [64][65]  (K tile == V tile, q=k=v)
    float* Ps   = sm + 2 * 64 * 65; // [64][65]
    float* lred = sm + 3 * 64 * 65; // [64][17]

    const int bh = blockIdx.y;          // 0..63
    const int b  = bh >> 4;
    const int h  = bh & 15;
    const int q0 = blockIdx.x << 6;     // query tile start
    const int tid = threadIdx.x;
    const int tx = tid & 15;
    const int ty = tid >> 4;

    const float* xb = x + (size_t)b * Sdim * Edim + h * DKdim;

    // Load Q tile [64 queries][64 dims]
#pragma unroll
    for (int i = 0; i < 16; i++) {
        int idx = tid + i * 256;
        int r = idx >> 6, c = idx & 63;
        Qs[r * 65 + c] = xb[(size_t)(q0 + r) * Edim + c];
    }

    float o[4][4] = {};
    float lsum[4] = {};
    __syncthreads();

    for (int k0 = 0; k0 < Sdim; k0 += 64) {
        // Load K (=V) tile
#pragma unroll
        for (int i = 0; i < 16; i++) {
            int idx = tid + i * 256;
            int r = idx >> 6, c = idx & 63;
            Ks[r * 65 + c] = xb[(size_t)(k0 + r) * Edim + c];
        }
        __syncthreads();

        // GEMM1: s = Q @ K^T  (64x64x64)
        float s[4][4] = {};
#pragma unroll 8
        for (int k = 0; k < 64; k++) {
            float a[4], bb[4];
#pragma unroll
            for (int r = 0; r < 4; r++) a[r] = Qs[(ty * 4 + r) * 65 + k];
#pragma unroll
            for (int c = 0; c < 4; c++) bb[c] = Ks[(tx * 4 + c) * 65 + k];
#pragma unroll
            for (int r = 0; r < 4; r++)
#pragma unroll
                for (int c = 0; c < 4; c++) s[r][c] += a[r] * bb[c];
        }

        // P = exp(s/8); accumulate row sums; stage P in smem for GEMM2
#pragma unroll
        for (int r = 0; r < 4; r++) {
#pragma unroll
            for (int c = 0; c < 4; c++) {
                float p = __expf(s[r][c] * 0.125f);
                Ps[(ty * 4 + r) * 65 + (tx * 4 + c)] = p;
                lsum[r] += p;
            }
        }
        __syncthreads();

        // GEMM2: o += P @ V   (V[k][d] = Ks[k][d])
#pragma unroll 8
        for (int k = 0; k < 64; k++) {
            float a[4], v[4];
#pragma unroll
            for (int r = 0; r < 4; r++) a[r] = Ps[(ty * 4 + r) * 65 + k];
#pragma unroll
            for (int c = 0; c < 4; c++) v[c] = Ks[k * 65 + (tx * 4 + c)];
#pragma unroll
            for (int r = 0; r < 4; r++)
#pragma unroll
                for (int c = 0; c < 4; c++) o[r][c] += a[r] * v[c];
        }
        __syncthreads();
    }

    // Reduce row sums l across the 16 tx-threads of each row
#pragma unroll
    for (int r = 0; r < 4; r++) lred[(ty * 4 + r) * 17 + tx] = lsum[r];
    __syncthreads();
    float linv[4];
#pragma unroll
    for (int r = 0; r < 4; r++) {
        float t = 0.0f;
#pragma unroll
        for (int j = 0; j < 16; j++) t += lred[(ty * 4 + r) * 17 + j];
        linv[r] = 1.0f / t;
    }

    // Write attn_out[b][q][h*64+d]
    float* ob = attn + ((size_t)b * Sdim + q0) * Edim + h * DKdim;
#pragma unroll
    for (int r = 0; r < 4; r++)
#pragma unroll
        for (int c = 0; c < 4; c++)
            ob[(size_t)(ty * 4 + r) * Edim + (tx * 4 + c)] = o[r][c] * linv[r];
}

// ---------------------------------------------------------------------------
// Residual + LayerNorm. One block per token (256 threads, 4 elems each).
// Optionally emits qout[t][q] = cos(h[t][q]) * cos(theta[q]) for q < 8.
// Safe in-place when a == out (resid == nullptr path).
// ---------------------------------------------------------------------------
__global__ void __launch_bounds__(256) ln_kernel(const float* __restrict__ a,
                                                 const float* __restrict__ resid,
                                                 const float* __restrict__ gamma,
                                                 const float* __restrict__ beta,
                                                 float* __restrict__ out,
                                                 float* __restrict__ qout,
                                                 const float* __restrict__ theta) {
    const int t = blockIdx.x;
    const int tid = threadIdx.x;
    const float* pa = a + (size_t)t * Edim;
    const float* pr = resid ? resid + (size_t)t * Edim : nullptr;

    float v[4];
    float s = 0.0f, s2 = 0.0f;
#pragma unroll
    for (int i = 0; i < 4; i++) {
        int e = tid + i * 256;
        float val = pa[e];
        if (pr) val += pr[e];
        v[i] = val;
        s += val;
        s2 += val * val;
    }
#pragma unroll
    for (int off = 16; off > 0; off >>= 1) {
        s  += __shfl_down_sync(0xffffffffu, s, off);
        s2 += __shfl_down_sync(0xffffffffu, s2, off);
    }
    __shared__ float r1[8], r2[8], stat[2];
    const int warp = tid >> 5, lane = tid & 31;
    if (lane == 0) { r1[warp] = s; r2[warp] = s2; }
    __syncthreads();
    if (tid == 0) {
        float S1 = 0.0f, S2 = 0.0f;
#pragma unroll
        for (int w = 0; w < 8; w++) { S1 += r1[w]; S2 += r2[w]; }
        float mu = S1 * (1.0f / Edim);
        float var = S2 * (1.0f / Edim) - mu * mu;
        stat[0] = mu;
        stat[1] = rsqrtf(var + EPSv);
    }
    __syncthreads();
    const float mu = stat[0], rs = stat[1];

    float* po = out + (size_t)t * Edim;
#pragma unroll
    for (int i = 0; i < 4; i++) {
        int e = tid + i * 256;
        po[e] = (v[i] - mu) * rs * gamma[e] + beta[e];
    }
    if (qout != nullptr && tid < NQdim) {
        float hv = (v[0] - mu) * rs * gamma[tid] + beta[tid];  // e == tid < 8
        qout[t * NQdim + tid] = cosf(hv) * cosf(theta[tid]);
    }
}

// ---------------------------------------------------------------------------
// Fused FFN: out = h + relu(qout @ w1^T + b1) @ w2^T + b2
// hid tile (64 tokens x 64 f) computed on the fly (134 MB never hits HBM).
// Block: 64x64 output tile, 256 threads, 4x4 micro-tiles, k over FFN=4096.
// ---------------------------------------------------------------------------
__global__ void __launch_bounds__(256) ffn_kernel(const float* __restrict__ qout,
                                                  const float* __restrict__ w1,
                                                  const float* __restrict__ b1,
                                                  const float* __restrict__ w2,
                                                  const float* __restrict__ b2,
                                                  const float* __restrict__ h,
                                                  float* __restrict__ out) {
    __shared__ float qs[64][8];
    __shared__ float w1s[64][9];
    __shared__ float b1s[64];
    __shared__ float hs[64][65];
    __shared__ float w2s[64][65];

    const int t0 = blockIdx.x << 6;   // token tile
    const int e0 = blockIdx.y << 6;   // output-dim tile
    const int tid = threadIdx.x;
    const int tx = tid & 15, ty = tid >> 4;

    // qout tile [64 tokens][8], loaded once
#pragma unroll
    for (int i = 0; i < 2; i++) {
        int idx = tid + i * 256;
        int r = idx >> 3, c = idx & 7;
        qs[r][c] = qout[(t0 + r) * NQdim + c];
    }

    float o[4][4] = {};
    for (int f0 = 0; f0 < FFNdim; f0 += 64) {
        __syncthreads();   // previous GEMM done (and first-iter qs visible)
        // w1 chunk [64 f][8] + b1 chunk
#pragma unroll
        for (int i = 0; i < 2; i++) {
            int idx = tid + i * 256;
            int r = idx >> 3, c = idx & 7;
            w1s[r][c] = w1[(f0 + r) * NQdim + c];
        }
        if (tid < 64) b1s[tid] = b1[f0 + tid];
        // w2 tile transposed into [f][e] (k-major for the GEMM)
#pragma unroll
        for (int i = 0; i < 16; i++) {
            int idx = tid + i * 256;
            int e = idx >> 6, f = idx & 63;
            w2s[f][e] = w2[(size_t)(e0 + e) * FFNdim + (f0 + f)];
        }
        __syncthreads();

        // hid tile: relu(qout . w1 + b1), 16 entries per thread
#pragma unroll
        for (int i = 0; i < 16; i++) {
            int idx = tid + i * 256;
            int r = idx >> 6, f = idx & 63;
            float acc = b1s[f];
#pragma unroll
            for (int q = 0; q < 8; q++) acc += qs[r][q] * w1s[f][q];
            hs[r][f] = fmaxf(acc, 0.0f);
        }
        __syncthreads();

        // o += hid @ w2s   (64x64x64)
#pragma unroll 8
        for (int k = 0; k < 64; k++) {
            float a[4], bb[4];
#pragma unroll
            for (int r = 0; r < 4; r++) a[r] = hs[ty * 4 + r][k];
#pragma unroll
            for (int c = 0; c < 4; c++) bb[c] = w2s[k][tx * 4 + c];
#pragma unroll
            for (int r = 0; r < 4; r++)
#pragma unroll
                for (int c = 0; c < 4; c++) o[r][c] += a[r] * bb[c];
        }
    }

    // Epilogue: + b2 + residual h, write pre-LN2 value into d_out
#pragma unroll
    for (int r = 0; r < 4; r++) {
#pragma unroll
        for (int c = 0; c < 4; c++) {
            size_t idx = (size_t)(t0 + ty * 4 + r) * Edim + (e0 + tx * 4 + c);
            out[idx] = o[r][c] + b2[e0 + tx * 4 + c] + h[idx];
        }
    }
}

// ---------------------------------------------------------------------------
extern "C" void kernel_launch(void* const* d_in, const int* in_sizes, int n_in,
                              void* d_out, int out_size) {
    const float* x      = (const float*)d_in[0];
    const float* theta  = (const float*)d_in[1];
    const float* w1     = (const float*)d_in[2];
    const float* b1     = (const float*)d_in[3];
    const float* w2     = (const float*)d_in[4];
    const float* b2     = (const float*)d_in[5];
    const float* gamma1 = (const float*)d_in[6];
    const float* beta1  = (const float*)d_in[7];
    const float* gamma2 = (const float*)d_in[8];
    const float* beta2  = (const float*)d_in[9];
    float* out = (float*)d_out;

    float *attn_p, *h_p, *qout_p;
    cudaGetSymbolAddress((void**)&attn_p, g_attn);
    cudaGetSymbolAddress((void**)&h_p, g_h);
    cudaGetSymbolAddress((void**)&qout_p, g_qout);

    const size_t attn_smem = (3 * 64 * 65 + 64 * 17) * sizeof(float);  // ~54.3 KB
    cudaFuncSetAttribute(attn_kernel, cudaFuncAttributeMaxDynamicSharedMemorySize,
                         (int)attn_smem);

    // 1) attention -> g_attn
    attn_kernel<<<dim3(Sdim / 64, Bdim * Hdim), 256, attn_smem>>>(x, attn_p);
    // 2) h = LN(x + attn), plus qout = cos(h[:, :8]) * cos(theta)
    ln_kernel<<<NTOK, 256>>>(x, attn_p, gamma1, beta1, h_p, qout_p, theta);
    // 3) d_out = h + FFN(h)   (fused FFN1+FFN2+bias+residual)
    ffn_kernel<<<dim3(NTOK / 64, Edim / 64), 256>>>(qout_p, w1, b1, w2, b2, h_p, out);
    // 4) d_out = LN(d_out), in place
    ln_kernel<<<NTOK, 256>>>(out, nullptr, gamma2, beta2, out, nullptr, nullptr);
}

// round 3
// speedup vs baseline: 3.3771x; 3.3771x over previous
#include <cuda_runtime.h>
#include <math.h>
#include <stdint.h>

// Problem dims (fixed by reference)
#define Bdim 4
#define Sdim 2048
#define Edim 1024
#define Hdim 16
#define DKdim 64
#define FFNdim 4096
#define NQdim 8
#define NTOK (Bdim * Sdim)
#define EPSv 1e-5f

// Scratch (alloc-free rule: __device__ globals)
__device__ float g_attn[(size_t)NTOK * Edim];    // 33.5 MB
__device__ float g_h[(size_t)NTOK * Edim];       // 33.5 MB
__device__ float g_qout[NTOK * NQdim];           // 256 KB
__device__ float g_hid[(size_t)NTOK * FFNdim];   // 134 MB (tf32-rounded)
__device__ float g_w2t[(size_t)Edim * FFNdim];   // 16.8 MB (tf32-rounded)
__device__ float g_xh[(size_t)NTOK * Edim];      // 33.5 MB (tf32 hi part of x)
__device__ float g_xl[(size_t)NTOK * Edim];      // 33.5 MB (tf32 lo part of x)

// ---------------------------------------------------------------------------
// Helpers
// ---------------------------------------------------------------------------
__device__ __forceinline__ uint32_t smem_u32(const void* p) {
    uint32_t a;
    asm("{ .reg .u64 t; cvta.to.shared.u64 t, %1; cvt.u32.u64 %0, t; }"
        : "=r"(a) : "l"(p));
    return a;
}
__device__ __forceinline__ float cvt_tf32(float v) {
    uint32_t t;
    asm("cvt.rna.tf32.f32 %0, %1;" : "=r"(t) : "f"(v));
    return __uint_as_float(t);
}
__device__ __forceinline__ void mma_tf32(float c[4], const uint32_t a[4],
                                         const uint32_t b[2]) {
    asm volatile(
        "mma.sync.aligned.m16n8k8.row.col.f32.tf32.tf32.f32 "
        "{%0,%1,%2,%3}, {%4,%5,%6,%7}, {%8,%9}, {%0,%1,%2,%3};"
        : "+f"(c[0]), "+f"(c[1]), "+f"(c[2]), "+f"(c[3])
        : "r"(a[0]), "r"(a[1]), "r"(a[2]), "r"(a[3]), "r"(b[0]), "r"(b[1]));
}
__device__ __forceinline__ void cp16(uint32_t dst, const void* src) {
    asm volatile("cp.async.ca.shared.global [%0], [%1], 16;" :: "r"(dst), "l"(src));
}
__device__ __forceinline__ void cp_commit() {
    asm volatile("cp.async.commit_group;" ::: "memory");
}
template <int N>
__device__ __forceinline__ void cp_wait() {
    asm volatile("cp.async.wait_group %0;" :: "n"(N) : "memory");
}

// ---------------------------------------------------------------------------
// x -> (xh, xl): tf32 split for 3xTF32 score GEMM
// ---------------------------------------------------------------------------
__global__ void __launch_bounds__(256) cvt_x_kernel(const float* __restrict__ x,
                                                    float* __restrict__ xh,
                                                    float* __restrict__ xl) {
    size_t i = ((size_t)blockIdx.x * 256 + threadIdx.x) * 4;
    float4 v = *(const float4*)(x + i);
    float4 hpart, lpart;
    hpart.x = cvt_tf32(v.x); lpart.x = cvt_tf32(v.x - hpart.x);
    hpart.y = cvt_tf32(v.y); lpart.y = cvt_tf32(v.y - hpart.y);
    hpart.z = cvt_tf32(v.z); lpart.z = cvt_tf32(v.z - hpart.z);
    hpart.w = cvt_tf32(v.w); lpart.w = cvt_tf32(v.w - hpart.w);
    *(float4*)(xh + i) = hpart;
    *(float4*)(xl + i) = lpart;
}

// ---------------------------------------------------------------------------
// w2 -> tf32-rounded copy
// ---------------------------------------------------------------------------
__global__ void __launch_bounds__(256) cvt_w2_kernel(const float* __restrict__ w2,
                                                     float* __restrict__ w2t) {
    size_t i = ((size_t)blockIdx.x * 256 + threadIdx.x) * 4;
    float4 v = *(const float4*)(w2 + i);
    float4 o;
    o.x = cvt_tf32(v.x); o.y = cvt_tf32(v.y);
    o.z = cvt_tf32(v.z); o.w = cvt_tf32(v.w);
    *(float4*)(w2t + i) = o;
}

// ---------------------------------------------------------------------------
// Attention with mma.sync tf32. Per block: one (b,h), 64-query tile.
// 128 threads = 4 warps in a 2x2 grid of 32x32 warp tiles.
// GEMM1 (scores) uses 3xTF32 split (hi/lo) for fp32-level accuracy.
// Unnormalized streaming softmax (scores <= ~15, fp32-safe).
// ---------------------------------------------------------------------------
#define ASTR 68   // smem row stride in floats (bank-conflict-free frag loads)

__global__ void __launch_bounds__(128) attn_kernel(const float* __restrict__ xh,
                                                   const float* __restrict__ xl,
                                                   float* __restrict__ attn) {
    extern __shared__ float sm[];
    float* Qh = sm;
    float* Ql = sm + 64 * ASTR;
    float* Kh = sm + 2 * 64 * ASTR;
    float* Kl = sm + 3 * 64 * ASTR;
    float* Ps = sm + 4 * 64 * ASTR;
    __shared__ float lred[64][2];

    const int bh = blockIdx.y, b = bh >> 4, h = bh & 15;
    const int q0 = blockIdx.x << 6;
    const int tid = threadIdx.x, lane = tid & 31, w = tid >> 5;
    const int mw = w >> 1, nw = w & 1;
    const int RM = mw * 32, CN = nw * 32;
    const int r0 = lane >> 2, c0 = lane & 3;

    const size_t xbase = (size_t)b * Sdim * Edim + h * DKdim;
    const float* xhb = xh + xbase;
    const float* xlb = xl + xbase;

    const uint32_t sQh = smem_u32(Qh), sQl = smem_u32(Ql);
    const uint32_t sKh = smem_u32(Kh), sKl = smem_u32(Kl);

    // Load Q tile (hi+lo): 64 rows x 16 16B-chunks each
#pragma unroll
    for (int i = 0; i < 8; i++) {
        int idx = tid + i * 128;
        int r = idx >> 4, ch = idx & 15;
        uint32_t off = (uint32_t)(r * ASTR * 4 + ch * 16);
        size_t g = (size_t)(q0 + r) * Edim + ch * 4;
        cp16(sQh + off, xhb + g);
        cp16(sQl + off, xlb + g);
    }
    cp_commit();

    float o[2][4][4] = {};
    float lsum[2][2] = {};

    for (int k0 = 0; k0 < Sdim; k0 += 64) {
        __syncthreads();  // Kh/Kl/Ps from previous tile fully consumed
#pragma unroll
        for (int i = 0; i < 8; i++) {
            int idx = tid + i * 128;
            int r = idx >> 4, ch = idx & 15;
            uint32_t off = (uint32_t)(r * ASTR * 4 + ch * 16);
            size_t g = (size_t)(k0 + r) * Edim + ch * 4;
            cp16(sKh + off, xhb + g);
            cp16(sKl + off, xlb + g);
        }
        cp_commit();
        cp_wait<0>();
        __syncthreads();

        // ---- GEMM1: S = Q K^T (3xTF32 split) ----
        float s[2][4][4] = {};
#pragma unroll
        for (int ks = 0; ks < 8; ks++) {
            const int kk = ks * 8 + c0;
            uint32_t ah[2][4], al[2][4];
#pragma unroll
            for (int mt = 0; mt < 2; mt++) {
                int rr = RM + mt * 16 + r0;
                ah[mt][0] = __float_as_uint(Qh[rr * ASTR + kk]);
                ah[mt][1] = __float_as_uint(Qh[(rr + 8) * ASTR + kk]);
                ah[mt][2] = __float_as_uint(Qh[rr * ASTR + kk + 4]);
                ah[mt][3] = __float_as_uint(Qh[(rr + 8) * ASTR + kk + 4]);
                al[mt][0] = __float_as_uint(Ql[rr * ASTR + kk]);
                al[mt][1] = __float_as_uint(Ql[(rr + 8) * ASTR + kk]);
                al[mt][2] = __float_as_uint(Ql[rr * ASTR + kk + 4]);
                al[mt][3] = __float_as_uint(Ql[(rr + 8) * ASTR + kk + 4]);
            }
#pragma unroll
            for (int nt = 0; nt < 4; nt++) {
                int nn = CN + nt * 8 + r0;
                uint32_t bhf[2], blf[2];
                bhf[0] = __float_as_uint(Kh[nn * ASTR + kk]);
                bhf[1] = __float_as_uint(Kh[nn * ASTR + kk + 4]);
                blf[0] = __float_as_uint(Kl[nn * ASTR + kk]);
                blf[1] = __float_as_uint(Kl[nn * ASTR + kk + 4]);
#pragma unroll
                for (int mt = 0; mt < 2; mt++) {
                    mma_tf32(s[mt][nt], ah[mt], bhf);
                    mma_tf32(s[mt][nt], ah[mt], blf);
                    mma_tf32(s[mt][nt], al[mt], bhf);
                }
            }
        }

        // ---- exp + stage P (tf32) + row-sum accumulate ----
#pragma unroll
        for (int mt = 0; mt < 2; mt++)
#pragma unroll
            for (int nt = 0; nt < 4; nt++)
#pragma unroll
                for (int j = 0; j < 4; j++) {
                    int rr = RM + mt * 16 + r0 + (j >> 1) * 8;
                    int cc = CN + nt * 8 + c0 * 2 + (j & 1);
                    float p = __expf(s[mt][nt][j] * 0.125f);
                    lsum[mt][j >> 1] += p;
                    Ps[rr * ASTR + cc] = cvt_tf32(p);
                }
        __syncthreads();  // P cols cross warp boundaries for GEMM2

        // ---- GEMM2: O += P V  (V = K tile, hi part) ----
#pragma unroll
        for (int ks = 0; ks < 8; ks++) {
            const int kk = ks * 8 + c0;
            uint32_t a[2][4];
#pragma unroll
            for (int mt = 0; mt < 2; mt++) {
                int rr = RM + mt * 16 + r0;
                a[mt][0] = __float_as_uint(Ps[rr * ASTR + kk]);
                a[mt][1] = __float_as_uint(Ps[(rr + 8) * ASTR + kk]);
                a[mt][2] = __float_as_uint(Ps[rr * ASTR + kk + 4]);
                a[mt][3] = __float_as_uint(Ps[(rr + 8) * ASTR + kk + 4]);
            }
#pragma unroll
            for (int nt = 0; nt < 4; nt++) {
                int nn = CN + nt * 8 + r0;
                uint32_t bb[2];
                bb[0] = __float_as_uint(Kh[kk * ASTR + nn]);
                bb[1] = __float_as_uint(Kh[(kk + 4) * ASTR + nn]);
                mma_tf32(o[0][nt], a[0], bb);
                mma_tf32(o[1][nt], a[1], bb);
            }
        }
    }

    // ---- final row-sum reduce (4 col-lanes, then across the 2 n-warps) ----
#pragma unroll
    for (int mt = 0; mt < 2; mt++)
#pragma unroll
        for (int hh = 0; hh < 2; hh++) {
            float v = lsum[mt][hh];
            v += __shfl_xor_sync(0xffffffffu, v, 1);
            v += __shfl_xor_sync(0xffffffffu, v, 2);
            lsum[mt][hh] = v;
        }
    if (c0 == 0) {
#pragma unroll
        for (int mt = 0; mt < 2; mt++)
#pragma unroll
            for (int hh = 0; hh < 2; hh++)
                lred[RM + mt * 16 + r0 + hh * 8][nw] = lsum[mt][hh];
    }
    __syncthreads();

    float* ob = attn + ((size_t)b * Sdim + q0) * Edim + h * DKdim;
#pragma unroll
    for (int mt = 0; mt < 2; mt++)
#pragma unroll
        for (int hh = 0; hh < 2; hh++) {
            int rr = RM + mt * 16 + r0 + hh * 8;
            float linv = 1.0f / (lred[rr][0] + lred[rr][1]);
#pragma unroll
            for (int nt = 0; nt < 4; nt++) {
                float2 v;
                v.x = o[mt][nt][hh * 2] * linv;
                v.y = o[mt][nt][hh * 2 + 1] * linv;
                *(float2*)(ob + (size_t)rr * Edim + CN + nt * 8 + c0 * 2) = v;
            }
        }
}

// ---------------------------------------------------------------------------
// Residual + LayerNorm (unchanged)
// ---------------------------------------------------------------------------
__global__ void __launch_bounds__(256) ln_kernel(const float* __restrict__ a,
                                                 const float* __restrict__ resid,
                                                 const float* __restrict__ gamma,
                                                 const float* __restrict__ beta,
                                                 float* __restrict__ out,
                                                 float* __restrict__ qout,
                                                 const float* __restrict__ theta) {
    const int t = blockIdx.x;
    const int tid = threadIdx.x;
    const float* pa = a + (size_t)t * Edim;
    const float* pr = resid ? resid + (size_t)t * Edim : nullptr;

    float v[4];
    float s = 0.0f, s2 = 0.0f;
#pragma unroll
    for (int i = 0; i < 4; i++) {
        int e = tid + i * 256;
        float val = pa[e];
        if (pr) val += pr[e];
        v[i] = val;
        s += val;
        s2 += val * val;
    }
#pragma unroll
    for (int off = 16; off > 0; off >>= 1) {
        s  += __shfl_down_sync(0xffffffffu, s, off);
        s2 += __shfl_down_sync(0xffffffffu, s2, off);
    }
    __shared__ float r1[8], r2[8], stat[2];
    const int warp = tid >> 5, lane = tid & 31;
    if (lane == 0) { r1[warp] = s; r2[warp] = s2; }
    __syncthreads();
    if (tid == 0) {
        float S1 = 0.0f, S2 = 0.0f;
#pragma unroll
        for (int wi = 0; wi < 8; wi++) { S1 += r1[wi]; S2 += r2[wi]; }
        float mu = S1 * (1.0f / Edim);
        float var = S2 * (1.0f / Edim) - mu * mu;
        stat[0] = mu;
        stat[1] = rsqrtf(var + EPSv);
    }
    __syncthreads();
    const float mu = stat[0], rs = stat[1];

    float* po = out + (size_t)t * Edim;
#pragma unroll
    for (int i = 0; i < 4; i++) {
        int e = tid + i * 256;
        po[e] = (v[i] - mu) * rs * gamma[e] + beta[e];
    }
    if (qout != nullptr && tid < NQdim) {
        float hv = (v[0] - mu) * rs * gamma[tid] + beta[tid];
        qout[t * NQdim + tid] = cosf(hv) * cosf(theta[tid]);
    }
}

// ---------------------------------------------------------------------------
// hid = relu(qout @ w1^T + b1), tf32-rounded -> g_hid [NTOK][FFN]
// ---------------------------------------------------------------------------
__global__ void __launch_bounds__(256) hid_kernel(const float* __restrict__ qout,
                                                  const float* __restrict__ w1,
                                                  const float* __restrict__ b1,
                                                  float* __restrict__ hid) {
    __shared__ float qs[64][8];
    const int tid = threadIdx.x;
    const int f = blockIdx.x * 256 + tid;
    const int t0 = blockIdx.y * 64;
#pragma unroll
    for (int i = 0; i < 2; i++) {
        int idx = tid + i * 256;
        qs[idx >> 3][idx & 7] = qout[(t0 + (idx >> 3)) * NQdim + (idx & 7)];
    }
    float4 wa = *(const float4*)(w1 + (size_t)f * NQdim);
    float4 wb = *(const float4*)(w1 + (size_t)f * NQdim + 4);
    float bb = b1[f];
    __syncthreads();
#pragma unroll 4
    for (int t = 0; t < 64; t++) {
        float acc = bb;
        acc += qs[t][0] * wa.x + qs[t][1] * wa.y + qs[t][2] * wa.z + qs[t][3] * wa.w;
        acc += qs[t][4] * wb.x + qs[t][5] * wb.y + qs[t][6] * wb.z + qs[t][7] * wb.w;
        hid[(size_t)(t0 + t) * FFNdim + f] = cvt_tf32(fmaxf(acc, 0.0f));
    }
}

// ---------------------------------------------------------------------------
// FFN2 via mma.sync tf32: out = h + hid @ w2t^T + b2
// CTA: 128 tokens x 128 e, 256 threads = 8 warps (32x64 warp tiles).
// Double-buffered cp.async over K chunks of 32.
// ---------------------------------------------------------------------------
#define FSTR 36               // smem row stride (floats)
#define FROWB (FSTR * 4)      // 144 bytes
#define FFN_SMEM (4 * 128 * FROWB)   // 73728 B

__global__ void __launch_bounds__(256) ffn2_gemm(const float* __restrict__ hid,
                                                 const float* __restrict__ w2t,
                                                 const float* __restrict__ b2,
                                                 const float* __restrict__ hres,
                                                 float* __restrict__ out) {
    extern __shared__ float sm[];
    const uint32_t sbase = smem_u32(sm);
    const int tid = threadIdx.x, lane = tid & 31, w = tid >> 5;
    const int mw = w >> 1, nw = w & 1;
    const int RM = mw * 32, CN = nw * 64;
    const int r0 = lane >> 2, c0 = lane & 3;
    const int e0 = blockIdx.x * 128;   // N fastest -> A rows shared in L2
    const int t0 = blockIdx.y * 128;

    float o[2][8][4] = {};

    // Stage s: A at s*128 rows, B at (2+s)*128 rows (row stride FROWB bytes)
#pragma unroll 1
    for (int kc = -1; kc < FFNdim / 32; kc++) {
        // issue loads for chunk kc+1 into buffer (kc+1)&1
        if (kc + 1 < FFNdim / 32) {
            const int lc = kc + 1, ls = lc & 1;
            uint32_t Ab = sbase + (uint32_t)ls * 128 * FROWB;
            uint32_t Bb = sbase + (uint32_t)(2 + ls) * 128 * FROWB;
#pragma unroll
            for (int i = 0; i < 4; i++) {
                int idx = tid + i * 256;
                int r = idx >> 3, ch = idx & 7;
                uint32_t off = (uint32_t)(r * FROWB + ch * 16);
                cp16(Ab + off, hid + (size_t)(t0 + r) * FFNdim + lc * 32 + ch * 4);
                cp16(Bb + off, w2t + (size_t)(e0 + r) * FFNdim + lc * 32 + ch * 4);
            }
            cp_commit();
        }
        if (kc < 0) continue;   // prologue: only the first load issued

        if (kc + 1 < FFNdim / 32) cp_wait<1>();
        else cp_wait<0>();
        __syncthreads();        // chunk-kc data visible to all warps

        const int s = kc & 1;
        const float* As = sm + s * 128 * FSTR;
        const float* Bs = sm + (2 + s) * 128 * FSTR;
#pragma unroll
        for (int ks = 0; ks < 4; ks++) {
            const int kk = ks * 8 + c0;
            uint32_t a[2][4];
#pragma unroll
            for (int mt = 0; mt < 2; mt++) {
                int rr = RM + mt * 16 + r0;
                a[mt][0] = __float_as_uint(As[rr * FSTR + kk]);
                a[mt][1] = __float_as_uint(As[(rr + 8) * FSTR + kk]);
                a[mt][2] = __float_as_uint(As[rr * FSTR + kk + 4]);
                a[mt][3] = __float_as_uint(As[(rr + 8) * FSTR + kk + 4]);
            }
#pragma unroll
            for (int nt = 0; nt < 8; nt++) {
                int nn = CN + nt * 8 + r0;
                uint32_t bb[2];
                bb[0] = __float_as_uint(Bs[nn * FSTR + kk]);
                bb[1] = __float_as_uint(Bs[nn * FSTR + kk + 4]);
                mma_tf32(o[0][nt], a[0], bb);
                mma_tf32(o[1][nt], a[1], bb);
            }
        }
        __syncthreads();        // all warps done with buffer s before overwrite
    }

    // Epilogue: + b2 + residual h
#pragma unroll
    for (int mt = 0; mt < 2; mt++)
#pragma unroll
        for (int hh = 0; hh < 2; hh++) {
            int tt = t0 + RM + mt * 16 + r0 + hh * 8;
#pragma unroll
            for (int nt = 0; nt < 8; nt++) {
                int ee = e0 + CN + nt * 8 + c0 * 2;
                float2 hv = *(const float2*)(hres + (size_t)tt * Edim + ee);
                float2 bv = *(const float2*)(b2 + ee);
                float2 ov;
                ov.x = o[mt][nt][hh * 2] + hv.x + bv.x;
                ov.y = o[mt][nt][hh * 2 + 1] + hv.y + bv.y;
                *(float2*)(out + (size_t)tt * Edim + ee) = ov;
            }
        }
}

// ---------------------------------------------------------------------------
extern "C" void kernel_launch(void* const* d_in, const int* in_sizes, int n_in,
                              void* d_out, int out_size) {
    const float* x      = (const float*)d_in[0];
    const float* theta  = (const float*)d_in[1];
    const float* w1     = (const float*)d_in[2];
    const float* b1     = (const float*)d_in[3];
    const float* w2     = (const float*)d_in[4];
    const float* b2     = (const float*)d_in[5];
    const float* gamma1 = (const float*)d_in[6];
    const float* beta1  = (const float*)d_in[7];
    const float* gamma2 = (const float*)d_in[8];
    const float* beta2  = (const float*)d_in[9];
    float* out = (float*)d_out;

    float *attn_p, *h_p, *qout_p, *hid_p, *w2t_p, *xh_p, *xl_p;
    cudaGetSymbolAddress((void**)&attn_p, g_attn);
    cudaGetSymbolAddress((void**)&h_p, g_h);
    cudaGetSymbolAddress((void**)&qout_p, g_qout);
    cudaGetSymbolAddress((void**)&hid_p, g_hid);
    cudaGetSymbolAddress((void**)&w2t_p, g_w2t);
    cudaGetSymbolAddress((void**)&xh_p, g_xh);
    cudaGetSymbolAddress((void**)&xl_p, g_xl);

    const int attn_smem = 5 * 64 * ASTR * 4;   // 87040 B
    cudaFuncSetAttribute(attn_kernel, cudaFuncAttributeMaxDynamicSharedMemorySize,
                         attn_smem);
    cudaFuncSetAttribute(ffn2_gemm, cudaFuncAttributeMaxDynamicSharedMemorySize,
                         FFN_SMEM);

    // 0) precision prep
    cvt_w2_kernel<<<(Edim * FFNdim) / 1024, 256>>>(w2, w2t_p);
    cvt_x_kernel<<<((size_t)NTOK * Edim) / 1024, 256>>>(x, xh_p, xl_p);
    // 1) attention (tensor cores, 3xTF32 scores) -> g_attn
    attn_kernel<<<dim3(Sdim / 64, Bdim * Hdim), 128, attn_smem>>>(xh_p, xl_p, attn_p);
    // 2) h = LN(x + attn), qout = cos(h[:, :8]) * cos(theta)
    ln_kernel<<<NTOK, 256>>>(x, attn_p, gamma1, beta1, h_p, qout_p, theta);
    // 3) hid = relu(qout @ w1^T + b1), tf32-rounded
    hid_kernel<<<dim3(FFNdim / 256, NTOK / 64), 256>>>(qout_p, w1, b1, hid_p);
    // 4) d_out = h + hid @ w2t^T + b2   (tensor cores)
    ffn2_gemm<<<dim3(Edim / 128, NTOK / 128), 256, FFN_SMEM>>>(hid_p, w2t_p, b2, h_p, out);
    // 5) d_out = LN(d_out), in place
    ln_kernel<<<NTOK, 256>>>(out, nullptr, gamma2, beta2, out, nullptr, nullptr);
}